// round 11
// baseline (speedup 1.0000x reference)
#include <cuda_runtime.h>
#include <cuda_bf16.h>
#include <cstdint>
#include <math.h>

// ---------------- problem constants ----------------
#define F_IN  128
#define D1    128
#define N_CLS 64
#define MAXN  50000
#define MAXE  800000
#define SCAN_CHUNK 4096
#define MAXB ((MAXN + SCAN_CHUNK - 1) / SCAN_CHUNK)
#define LDA 136   // padded smem row pitch in bf16 (272 B)

// ---------------- device scratch ----------------
__device__ float g_h1[MAXN * D1];
__device__ float g_h2[MAXN * N_CLS];
__device__ int   g_deg[MAXN];
__device__ float g_dis[MAXN];
__device__ int   g_rowptr[MAXN + 1];
__device__ int   g_cursor[MAXN];
__device__ int2  g_edge[MAXE];          // (src, norm-bits)
__device__ int   g_bsum[MAXB];
// bf16-split transposed weights, plain [N][128] row-major
__device__ __nv_bfloat16 g_w1h[128 * 128];
__device__ __nv_bfloat16 g_w1l[128 * 128];
__device__ __nv_bfloat16 g_w2h[64 * 128];
__device__ __nv_bfloat16 g_w2l[64 * 128];

// ---------------- helpers ----------------
__device__ __forceinline__ uint32_t smem_u32(const void* p) {
    uint32_t a;
    asm("{ .reg .u64 t; cvta.to.shared.u64 t, %1; cvt.u32.u64 %0, t; }" : "=r"(a) : "l"(p));
    return a;
}
__device__ __forceinline__ void ldmatrix_x4(uint32_t& r0, uint32_t& r1, uint32_t& r2,
                                            uint32_t& r3, uint32_t addr) {
    asm volatile("ldmatrix.sync.aligned.m8n8.x4.shared.b16 {%0,%1,%2,%3}, [%4];"
                 : "=r"(r0), "=r"(r1), "=r"(r2), "=r"(r3) : "r"(addr));
}
__device__ __forceinline__ void ldmatrix_x2(uint32_t& r0, uint32_t& r1, uint32_t addr) {
    asm volatile("ldmatrix.sync.aligned.m8n8.x2.shared.b16 {%0,%1}, [%2];"
                 : "=r"(r0), "=r"(r1) : "r"(addr));
}
__device__ __forceinline__ void mma_bf16(float* c, const uint32_t* a, uint32_t b0, uint32_t b1) {
    asm volatile("mma.sync.aligned.m16n8k16.row.col.f32.bf16.bf16.f32 "
                 "{%0,%1,%2,%3}, {%4,%5,%6,%7}, {%8,%9}, {%0,%1,%2,%3};"
                 : "+f"(c[0]), "+f"(c[1]), "+f"(c[2]), "+f"(c[3])
                 : "r"(a[0]), "r"(a[1]), "r"(a[2]), "r"(a[3]), "r"(b0), "r"(b1));
}
__device__ __forceinline__ uint32_t pack_bf16x2(__nv_bfloat16 lo, __nv_bfloat16 hi) {
    return ((uint32_t)__bfloat16_as_ushort(hi) << 16) | (uint32_t)__bfloat16_as_ushort(lo);
}

// ---------------- weight prep: transpose + bf16 split ----------------
__global__ void k_prep_w(const float* __restrict__ W1, const float* __restrict__ W2) {
    int idx = blockIdx.x * blockDim.x + threadIdx.x;
    if (idx < 128 * 128) {
        int nn = idx >> 7, k = idx & 127;
        float w = W1[k * 128 + nn];
        __nv_bfloat16 h = __float2bfloat16(w);
        g_w1h[idx] = h;
        g_w1l[idx] = __float2bfloat16(w - __bfloat162float(h));
    } else if (idx < 128 * 128 + 64 * 128) {
        int j = idx - 16384;
        int nn = j >> 7, k = j & 127;
        float w = W2[k * 64 + nn];
        __nv_bfloat16 h = __float2bfloat16(w);
        g_w2h[j] = h;
        g_w2l[j] = __float2bfloat16(w - __bfloat162float(h));
    }
}

// ---------------- HMMA GEMM: C[M,N] = A[M,128] @ Wt[N,128]^T, bf16 split ----------------
// block = 256 threads (8 warps), M-tile 128; warp w -> rows 16w..16w+15, all N.
template <int N>
__global__ void __launch_bounds__(256) k_gemm_tc(const float* __restrict__ A,
                                                 const __nv_bfloat16* __restrict__ Bh,
                                                 const __nv_bfloat16* __restrict__ Bl,
                                                 float* __restrict__ C, int M) {
    constexpr int NT = N / 8;
    constexpr int A_ELE = 128 * LDA;
    constexpr int B_ELE = N * LDA;
    extern __shared__ __nv_bfloat16 sm[];
    __nv_bfloat16* sAh = sm;
    __nv_bfloat16* sAl = sm + A_ELE;
    __nv_bfloat16* sBh = sm + 2 * A_ELE;
    __nv_bfloat16* sBl = sm + 2 * A_ELE + B_ELE;

    int tid = threadIdx.x, wid = tid >> 5, lane = tid & 31;
    int row0 = blockIdx.x * 128;

    {
        const uint4* bh = (const uint4*)Bh;
        const uint4* bl = (const uint4*)Bl;
        for (int i = tid; i < N * 16; i += 256) {
            int r = i >> 4, c = i & 15;
            int d = r * LDA + c * 8;
            *(uint4*)(sBh + d) = bh[i];
            *(uint4*)(sBl + d) = bl[i];
        }
    }
    {
        for (int i = tid; i < 128 * 32; i += 256) {
            int r = i >> 5, c = i & 31;
            int grow = row0 + r;
            float4 f = (grow < M) ? ((const float4*)A)[(size_t)grow * 32 + c]
                                  : make_float4(0.f, 0.f, 0.f, 0.f);
            __nv_bfloat16 hx = __float2bfloat16(f.x), hy = __float2bfloat16(f.y);
            __nv_bfloat16 hz = __float2bfloat16(f.z), hw = __float2bfloat16(f.w);
            uint32_t h01 = pack_bf16x2(hx, hy), h23 = pack_bf16x2(hz, hw);
            uint32_t l01 = pack_bf16x2(__float2bfloat16(f.x - __bfloat162float(hx)),
                                       __float2bfloat16(f.y - __bfloat162float(hy)));
            uint32_t l23 = pack_bf16x2(__float2bfloat16(f.z - __bfloat162float(hz)),
                                       __float2bfloat16(f.w - __bfloat162float(hw)));
            int d = r * LDA + c * 4;
            *(uint32_t*)(sAh + d) = h01; *(uint32_t*)(sAh + d + 2) = h23;
            *(uint32_t*)(sAl + d) = l01; *(uint32_t*)(sAl + d + 2) = l23;
        }
    }
    __syncthreads();

    uint32_t aOff = (uint32_t)(wid * 16 + (lane & 15)) * (LDA * 2) + (uint32_t)(lane >> 4) * 16;
    uint32_t ah_base = smem_u32(sAh) + aOff;
    uint32_t al_base = smem_u32(sAl) + aOff;
    uint32_t bOff = (uint32_t)(lane & 7) * (LDA * 2) + (uint32_t)((lane >> 3) & 1) * 16;
    uint32_t bh_base = smem_u32(sBh) + bOff;
    uint32_t bl_base = smem_u32(sBl) + bOff;

    float acc[NT][4];
    #pragma unroll
    for (int t = 0; t < NT; t++) { acc[t][0] = acc[t][1] = acc[t][2] = acc[t][3] = 0.f; }

    #pragma unroll
    for (int kk = 0; kk < 8; kk++) {
        uint32_t ah[4], al[4];
        ldmatrix_x4(ah[0], ah[1], ah[2], ah[3], ah_base + kk * 32);
        ldmatrix_x4(al[0], al[1], al[2], al[3], al_base + kk * 32);
        #pragma unroll
        for (int t = 0; t < NT; t++) {
            uint32_t b0, b1, c0, c1;
            uint32_t boff = (uint32_t)t * 8 * (LDA * 2) + kk * 32;
            ldmatrix_x2(b0, b1, bh_base + boff);
            ldmatrix_x2(c0, c1, bl_base + boff);
            mma_bf16(acc[t], ah, b0, b1);
            mma_bf16(acc[t], ah, c0, c1);
            mma_bf16(acc[t], al, b0, b1);
        }
    }

    int g = lane >> 2, tig = lane & 3;
    int r0 = row0 + wid * 16 + g;
    int r1 = r0 + 8;
    #pragma unroll
    for (int t = 0; t < NT; t++) {
        int col = t * 8 + tig * 2;
        if (r0 < M) *(float2*)(C + (size_t)r0 * N + col) = make_float2(acc[t][0], acc[t][1]);
        if (r1 < M) *(float2*)(C + (size_t)r1 * N + col) = make_float2(acc[t][2], acc[t][3]);
    }
}

// ---------------- FUSED: agg(h1)+bias+relu -> smem bf16 tile -> GEMM2 ----------------
// block = 256 threads (8 warps); 128 nodes per CTA; warp w aggregates nodes
// row0+16w .. row0+16w+15 directly into the A tile, then HMMA to C[M,N].
template <int N>
__global__ void __launch_bounds__(256) k_agg_gemm(const float* __restrict__ h,
                                                  const float* __restrict__ bias,
                                                  const __nv_bfloat16* __restrict__ Bh,
                                                  const __nv_bfloat16* __restrict__ Bl,
                                                  float* __restrict__ C, int M) {
    constexpr int NT = N / 8;
    constexpr int A_ELE = 128 * LDA;
    constexpr int B_ELE = N * LDA;
    extern __shared__ __nv_bfloat16 sm[];
    __nv_bfloat16* sAh = sm;
    __nv_bfloat16* sAl = sm + A_ELE;
    __nv_bfloat16* sBh = sm + 2 * A_ELE;
    __nv_bfloat16* sBl = sm + 2 * A_ELE + B_ELE;

    int tid = threadIdx.x, wid = tid >> 5, lane = tid & 31;
    int row0 = blockIdx.x * 128;

    // stage B
    {
        const uint4* bh = (const uint4*)Bh;
        const uint4* bl = (const uint4*)Bl;
        for (int i = tid; i < N * 16; i += 256) {
            int r = i >> 4, c = i & 15;
            int d = r * LDA + c * 8;
            *(uint4*)(sBh + d) = bh[i];
            *(uint4*)(sBl + d) = bl[i];
        }
    }

    // aggregation phase: warp w handles 16 nodes
    const float4* hv = (const float4*)h;
    float4 b = ((const float4*)bias)[lane];
    for (int j = 0; j < 16; j++) {
        int r = wid * 16 + j;           // local tile row
        int node = row0 + r;
        float4 acc = make_float4(0.f, 0.f, 0.f, 0.f);
        if (node < M) {
            float d = g_dis[node];
            float4 v = hv[node * 32 + lane];
            float sn = d * d;
            acc = make_float4(sn * v.x, sn * v.y, sn * v.z, sn * v.w);
            int e = g_rowptr[node], e1 = g_rowptr[node + 1];
            for (; e + 4 <= e1; e += 4) {
                int2 q0 = g_edge[e + 0], q1 = g_edge[e + 1];
                int2 q2 = g_edge[e + 2], q3 = g_edge[e + 3];
                float n0 = __int_as_float(q0.y), n1 = __int_as_float(q1.y);
                float n2 = __int_as_float(q2.y), n3 = __int_as_float(q3.y);
                float4 v0 = hv[q0.x * 32 + lane];
                float4 v1 = hv[q1.x * 32 + lane];
                float4 v2 = hv[q2.x * 32 + lane];
                float4 v3 = hv[q3.x * 32 + lane];
                acc.x += n0 * v0.x + n1 * v1.x + n2 * v2.x + n3 * v3.x;
                acc.y += n0 * v0.y + n1 * v1.y + n2 * v2.y + n3 * v3.y;
                acc.z += n0 * v0.z + n1 * v1.z + n2 * v2.z + n3 * v3.z;
                acc.w += n0 * v0.w + n1 * v1.w + n2 * v2.w + n3 * v3.w;
            }
            for (; e < e1; e++) {
                int2 q = g_edge[e];
                float nm = __int_as_float(q.y);
                float4 vv = hv[q.x * 32 + lane];
                acc.x += nm * vv.x; acc.y += nm * vv.y;
                acc.z += nm * vv.z; acc.w += nm * vv.w;
            }
            acc.x = fmaxf(acc.x + b.x, 0.f);
            acc.y = fmaxf(acc.y + b.y, 0.f);
            acc.z = fmaxf(acc.z + b.z, 0.f);
            acc.w = fmaxf(acc.w + b.w, 0.f);
        }
        // convert to bf16 hi/lo, store into tile row r at cols lane*4..lane*4+3
        __nv_bfloat16 hx = __float2bfloat16(acc.x), hy = __float2bfloat16(acc.y);
        __nv_bfloat16 hz = __float2bfloat16(acc.z), hw = __float2bfloat16(acc.w);
        uint32_t h01 = pack_bf16x2(hx, hy), h23 = pack_bf16x2(hz, hw);
        uint32_t l01 = pack_bf16x2(__float2bfloat16(acc.x - __bfloat162float(hx)),
                                   __float2bfloat16(acc.y - __bfloat162float(hy)));
        uint32_t l23 = pack_bf16x2(__float2bfloat16(acc.z - __bfloat162float(hz)),
                                   __float2bfloat16(acc.w - __bfloat162float(hw)));
        int d = r * LDA + lane * 4;
        *(uint32_t*)(sAh + d) = h01; *(uint32_t*)(sAh + d + 2) = h23;
        *(uint32_t*)(sAl + d) = l01; *(uint32_t*)(sAl + d + 2) = l23;
    }
    __syncthreads();

    // HMMA phase
    uint32_t aOff = (uint32_t)(wid * 16 + (lane & 15)) * (LDA * 2) + (uint32_t)(lane >> 4) * 16;
    uint32_t ah_base = smem_u32(sAh) + aOff;
    uint32_t al_base = smem_u32(sAl) + aOff;
    uint32_t bOff = (uint32_t)(lane & 7) * (LDA * 2) + (uint32_t)((lane >> 3) & 1) * 16;
    uint32_t bh_base = smem_u32(sBh) + bOff;
    uint32_t bl_base = smem_u32(sBl) + bOff;

    float acc[NT][4];
    #pragma unroll
    for (int t = 0; t < NT; t++) { acc[t][0] = acc[t][1] = acc[t][2] = acc[t][3] = 0.f; }

    #pragma unroll
    for (int kk = 0; kk < 8; kk++) {
        uint32_t ah[4], al[4];
        ldmatrix_x4(ah[0], ah[1], ah[2], ah[3], ah_base + kk * 32);
        ldmatrix_x4(al[0], al[1], al[2], al[3], al_base + kk * 32);
        #pragma unroll
        for (int t = 0; t < NT; t++) {
            uint32_t b0, b1, c0, c1;
            uint32_t boff = (uint32_t)t * 8 * (LDA * 2) + kk * 32;
            ldmatrix_x2(b0, b1, bh_base + boff);
            ldmatrix_x2(c0, c1, bl_base + boff);
            mma_bf16(acc[t], ah, b0, b1);
            mma_bf16(acc[t], ah, c0, c1);
            mma_bf16(acc[t], al, b0, b1);
        }
    }

    int g = lane >> 2, tig = lane & 3;
    int r0 = row0 + wid * 16 + g;
    int r1 = r0 + 8;
    #pragma unroll
    for (int t = 0; t < NT; t++) {
        int col = t * 8 + tig * 2;
        if (r0 < M) *(float2*)(C + (size_t)r0 * N + col) = make_float2(acc[t][0], acc[t][1]);
        if (r1 < M) *(float2*)(C + (size_t)r1 * N + col) = make_float2(acc[t][2], acc[t][3]);
    }
}

// ---------------- degree count (deg zeroed by memset; self-loop folded in scan) ----------------
__global__ void k_deg_count(const int* __restrict__ dst, int E, int n) {
    int e = blockIdx.x * blockDim.x + threadIdx.x;
    if (e >= E) return;
    int d = dst[e];
    if ((unsigned)d < (unsigned)n) atomicAdd(&g_deg[d], 1);
}

// ---------------- two-level scan (row length = raw count; dis = rsqrt(raw+1)) ----------------
__global__ void __launch_bounds__(1024) k_scan_blocks(int n) {
    __shared__ int wsum[32];
    int tid = threadIdx.x, lane = tid & 31, wid = tid >> 5;
    int base = blockIdx.x * SCAN_CHUNK + tid * 4;
    int v[4];
    #pragma unroll
    for (int j = 0; j < 4; j++) {
        int i = base + j;
        int raw = (i < n) ? g_deg[i] : 0;
        v[j] = raw;
        if (i < n) g_dis[i] = rsqrtf((float)(raw + 1));
    }
    int tsum = v[0] + v[1] + v[2] + v[3];
    int x = tsum;
    #pragma unroll
    for (int off = 1; off < 32; off <<= 1) {
        int y = __shfl_up_sync(0xffffffffu, x, off);
        if (lane >= off) x += y;
    }
    if (lane == 31) wsum[wid] = x;
    __syncthreads();
    if (wid == 0) {
        int w = wsum[lane];
        #pragma unroll
        for (int off = 1; off < 32; off <<= 1) {
            int y = __shfl_up_sync(0xffffffffu, w, off);
            if (lane >= off) w += y;
        }
        wsum[lane] = w;
    }
    __syncthreads();
    int e = (wid ? wsum[wid - 1] : 0) + (x - tsum);
    #pragma unroll
    for (int j = 0; j < 4; j++) {
        int i = base + j;
        if (i < n) g_rowptr[i] = e;
        e += v[j];
    }
    if (tid == 1023) g_bsum[blockIdx.x] = wsum[31];
}

__global__ void k_scan_add(int n, int nb) {
    __shared__ int carry_s;
    int i = blockIdx.x * blockDim.x + threadIdx.x;
    int chunk = (blockIdx.x * blockDim.x) >> 12;
    if (threadIdx.x == 0) {
        int c = 0;
        for (int j = 0; j < chunk; j++) c += g_bsum[j];
        carry_s = c;
        if (blockIdx.x == 0) {
            int t = 0;
            for (int j = 0; j < nb; j++) t += g_bsum[j];
            g_rowptr[n] = t;
        }
    }
    __syncthreads();
    if (i >= n) return;
    int r = g_rowptr[i] + carry_s;
    g_rowptr[i] = r;
    g_cursor[i] = r;
}

// ---------------- scatter (packed src+norm) ----------------
__global__ void k_scatter(const int* __restrict__ src,
                          const int* __restrict__ dst, int E, int n) {
    int e = blockIdx.x * blockDim.x + threadIdx.x;
    if (e >= E) return;
    int s = src[e];
    int d = dst[e];
    if ((unsigned)s >= (unsigned)n || (unsigned)d >= (unsigned)n) return;
    int pos = atomicAdd(&g_cursor[d], 1);
    g_edge[pos] = make_int2(s, __float_as_int(g_dis[s] * g_dis[d]));
}

// ---------------- aggregation: warp/node, 64 features ----------------
template <bool RELU>
__global__ void k_agg64(const float* __restrict__ h,
                        const float* __restrict__ bias,
                        float* __restrict__ out, int n) {
    int gwarp = (blockIdx.x * blockDim.x + threadIdx.x) >> 5;
    if (gwarp >= n) return;
    int lane = threadIdx.x & 31;
    const float2* hv = (const float2*)h;
    float d = g_dis[gwarp];
    float2 v = hv[gwarp * 32 + lane];
    float sn = d * d;
    float2 acc = make_float2(sn * v.x, sn * v.y);
    int e = g_rowptr[gwarp], e1 = g_rowptr[gwarp + 1];
    for (; e + 4 <= e1; e += 4) {
        int2 q0 = g_edge[e + 0], q1 = g_edge[e + 1], q2 = g_edge[e + 2], q3 = g_edge[e + 3];
        float n0 = __int_as_float(q0.y), n1 = __int_as_float(q1.y);
        float n2 = __int_as_float(q2.y), n3 = __int_as_float(q3.y);
        float2 v0 = hv[q0.x * 32 + lane];
        float2 v1 = hv[q1.x * 32 + lane];
        float2 v2 = hv[q2.x * 32 + lane];
        float2 v3 = hv[q3.x * 32 + lane];
        acc.x += n0 * v0.x + n1 * v1.x + n2 * v2.x + n3 * v3.x;
        acc.y += n0 * v0.y + n1 * v1.y + n2 * v2.y + n3 * v3.y;
    }
    for (; e < e1; e++) {
        int2 q = g_edge[e];
        float nm = __int_as_float(q.y);
        float2 vv = hv[q.x * 32 + lane];
        acc.x += nm * vv.x; acc.y += nm * vv.y;
    }
    float2 b = ((const float2*)bias)[lane];
    acc.x += b.x; acc.y += b.y;
    if (RELU) { acc.x = fmaxf(acc.x, 0.f); acc.y = fmaxf(acc.y, 0.f); }
    ((float2*)out)[gwarp * 32 + lane] = acc;
}

// ---------------- launch ----------------
extern "C" void kernel_launch(void* const* d_in, const int* in_sizes, int n_in,
                              void* d_out, int out_size) {
    const float* x    = (const float*)d_in[0];
    const int*   eidx = (const int*)d_in[1];
    const float* W1   = (const float*)d_in[2];
    const float* b1   = (const float*)d_in[3];
    const float* W2   = (const float*)d_in[4];
    const float* b2   = (const float*)d_in[5];
    float*       out  = (float*)d_out;

    int n = in_sizes[0] / F_IN;
    int E = in_sizes[1] / 2;
    const int* src = eidx;
    const int* dst = eidx + E;
    int nb = (n + SCAN_CHUNK - 1) / SCAN_CHUNK;

    const int SMEM1 = (2 * 128 * LDA + 2 * 128 * LDA) * 2;   // 139264 B
    const int SMEM2 = (2 * 128 * LDA + 2 * 64 * LDA) * 2;    // 104448 B
    cudaFuncSetAttribute(k_gemm_tc<128>, cudaFuncAttributeMaxDynamicSharedMemorySize, SMEM1);
    cudaFuncSetAttribute(k_agg_gemm<64>, cudaFuncAttributeMaxDynamicSharedMemorySize, SMEM2);

    float* h1;  cudaGetSymbolAddress((void**)&h1, g_h1);
    float* h2;  cudaGetSymbolAddress((void**)&h2, g_h2);
    int* degp;  cudaGetSymbolAddress((void**)&degp, g_deg);
    __nv_bfloat16 *w1h, *w1l, *w2h, *w2l;
    cudaGetSymbolAddress((void**)&w1h, g_w1h);
    cudaGetSymbolAddress((void**)&w1l, g_w1l);
    cudaGetSymbolAddress((void**)&w2h, g_w2h);
    cudaGetSymbolAddress((void**)&w2l, g_w2l);

    // graph structure build
    k_prep_w<<<96, 256>>>(W1, W2);
    cudaMemsetAsync(degp, 0, (size_t)n * sizeof(int), 0);
    k_deg_count<<<(E + 255) / 256, 256>>>(dst, E, n);
    k_scan_blocks<<<nb, 1024>>>(n);
    k_scan_add<<<(n + 255) / 256, 256>>>(n, nb);
    k_scatter<<<(E + 255) / 256, 256>>>(src, dst, E, n);

    int aggBlocks = (n + 7) / 8;
    int gemmBlocks = (n + 127) / 128;

    // layer 1 GEMM
    k_gemm_tc<128><<<gemmBlocks, 256, SMEM1>>>(x, w1h, w1l, h1, n);
    // fused: agg(h1)+b1+relu -> GEMM2 -> h2
    k_agg_gemm<64><<<gemmBlocks, 256, SMEM2>>>(h1, b1, w2h, w2l, h2, n);
    // final aggregation
    k_agg64<false><<<aggBlocks, 256>>>(h2, b2, out, n);
}

// round 12
// speedup vs baseline: 1.2231x; 1.2231x over previous
#include <cuda_runtime.h>
#include <cuda_bf16.h>
#include <cstdint>
#include <math.h>

// ---------------- problem constants ----------------
#define F_IN  128
#define D1    128
#define N_CLS 64
#define MAXN  50000
#define MAXE  800000
#define SCAN_CHUNK 4096
#define MAXB ((MAXN + SCAN_CHUNK - 1) / SCAN_CHUNK)
#define LDA 136   // padded smem row pitch in bf16 (272 B)
#define W_ELEMS (128 * 128 + 64 * 128)   // 24576

// ---------------- device scratch ----------------
__device__ float g_h1[MAXN * D1];
__device__ float g_a1[MAXN * D1];
__device__ float g_h2[MAXN * N_CLS];
__device__ int   g_deg[MAXN];
__device__ float g_dis[MAXN];
__device__ int   g_rowptr[MAXN + 1];
__device__ int   g_cursor[MAXN];
__device__ int2  g_edge[MAXE];                 // (src, norm-bits)
__device__ unsigned long long g_state[MAXB];   // lookback: flag<<32 | value
// bf16-split transposed weights, plain [N][128] row-major
__device__ __nv_bfloat16 g_w1h[128 * 128];
__device__ __nv_bfloat16 g_w1l[128 * 128];
__device__ __nv_bfloat16 g_w2h[64 * 128];
__device__ __nv_bfloat16 g_w2l[64 * 128];

// ---------------- helpers ----------------
__device__ __forceinline__ uint32_t smem_u32(const void* p) {
    uint32_t a;
    asm("{ .reg .u64 t; cvta.to.shared.u64 t, %1; cvt.u32.u64 %0, t; }" : "=r"(a) : "l"(p));
    return a;
}
__device__ __forceinline__ void ldmatrix_x4(uint32_t& r0, uint32_t& r1, uint32_t& r2,
                                            uint32_t& r3, uint32_t addr) {
    asm volatile("ldmatrix.sync.aligned.m8n8.x4.shared.b16 {%0,%1,%2,%3}, [%4];"
                 : "=r"(r0), "=r"(r1), "=r"(r2), "=r"(r3) : "r"(addr));
}
__device__ __forceinline__ void ldmatrix_x2(uint32_t& r0, uint32_t& r1, uint32_t addr) {
    asm volatile("ldmatrix.sync.aligned.m8n8.x2.shared.b16 {%0,%1}, [%2];"
                 : "=r"(r0), "=r"(r1) : "r"(addr));
}
__device__ __forceinline__ void mma_bf16(float* c, const uint32_t* a, uint32_t b0, uint32_t b1) {
    asm volatile("mma.sync.aligned.m16n8k16.row.col.f32.bf16.bf16.f32 "
                 "{%0,%1,%2,%3}, {%4,%5,%6,%7}, {%8,%9}, {%0,%1,%2,%3};"
                 : "+f"(c[0]), "+f"(c[1]), "+f"(c[2]), "+f"(c[3])
                 : "r"(a[0]), "r"(a[1]), "r"(a[2]), "r"(a[3]), "r"(b0), "r"(b1));
}
__device__ __forceinline__ uint32_t pack_bf16x2(__nv_bfloat16 lo, __nv_bfloat16 hi) {
    return ((uint32_t)__bfloat16_as_ushort(hi) << 16) | (uint32_t)__bfloat16_as_ushort(lo);
}

// ---------------- fused prep: weight split/transpose + degree count + state zero ----------------
__global__ void k_prep(const float* __restrict__ W1, const float* __restrict__ W2,
                       const int* __restrict__ dst, int E, int n) {
    int idx = blockIdx.x * blockDim.x + threadIdx.x;
    if (idx < MAXB) g_state[idx] = 0ull;
    if (idx < 128 * 128) {
        int nn = idx >> 7, k = idx & 127;
        float w = W1[k * 128 + nn];
        __nv_bfloat16 h = __float2bfloat16(w);
        g_w1h[idx] = h;
        g_w1l[idx] = __float2bfloat16(w - __bfloat162float(h));
    } else if (idx < W_ELEMS) {
        int j = idx - 16384;
        int nn = j >> 7, k = j & 127;
        float w = W2[k * 64 + nn];
        __nv_bfloat16 h = __float2bfloat16(w);
        g_w2h[j] = h;
        g_w2l[j] = __float2bfloat16(w - __bfloat162float(h));
    } else {
        int e = idx - W_ELEMS;
        if (e < E) {
            int d = dst[e];
            if ((unsigned)d < (unsigned)n) atomicAdd(&g_deg[d], 1);
        }
    }
}

// ---------------- single-pass decoupled-lookback scan ----------------
// raw counts (deg memset to 0); row length = raw, dis = rsqrt(raw+1) [self loop].
__global__ void __launch_bounds__(1024) k_scan(int n, int nb) {
    __shared__ int wsum[32];
    __shared__ int carry_s;
    int tid = threadIdx.x, lane = tid & 31, wid = tid >> 5;
    int bid = blockIdx.x;
    int base = bid * SCAN_CHUNK + tid * 4;

    int v[4];
    #pragma unroll
    for (int j = 0; j < 4; j++) {
        int i = base + j;
        int raw = (i < n) ? g_deg[i] : 0;
        v[j] = raw;
        if (i < n) g_dis[i] = rsqrtf((float)(raw + 1));
    }
    int tsum = v[0] + v[1] + v[2] + v[3];
    int x = tsum;
    #pragma unroll
    for (int off = 1; off < 32; off <<= 1) {
        int y = __shfl_up_sync(0xffffffffu, x, off);
        if (lane >= off) x += y;
    }
    if (lane == 31) wsum[wid] = x;
    __syncthreads();
    if (wid == 0) {
        int w = wsum[lane];
        #pragma unroll
        for (int off = 1; off < 32; off <<= 1) {
            int y = __shfl_up_sync(0xffffffffu, w, off);
            if (lane >= off) w += y;
        }
        wsum[lane] = w;
    }
    __syncthreads();
    int total = wsum[31];
    int excl = (wid ? wsum[wid - 1] : 0) + (x - tsum);

    if (tid == 0) {
        if (bid == 0) {
            atomicExch(&g_state[0], (2ull << 32) | (unsigned long long)(unsigned)total);
            carry_s = 0;
        } else {
            atomicExch(&g_state[bid], (1ull << 32) | (unsigned long long)(unsigned)total);
            int carry = 0;
            for (int j = bid - 1; j >= 0; j--) {
                unsigned long long s;
                do { s = atomicAdd(&g_state[j], 0ull); } while ((s >> 32) == 0ull);
                carry += (int)(unsigned)s;
                if ((s >> 32) == 2ull) break;
            }
            atomicExch(&g_state[bid], (2ull << 32) | (unsigned long long)(unsigned)(total + carry));
            carry_s = carry;
        }
    }
    __syncthreads();

    int e = excl + carry_s;
    #pragma unroll
    for (int j = 0; j < 4; j++) {
        int i = base + j;
        if (i < n) { g_rowptr[i] = e; g_cursor[i] = e; }
        e += v[j];
    }
    if (bid == nb - 1 && tid == 1023) g_rowptr[n] = carry_s + total;
}

// ---------------- scatter (packed src+norm) ----------------
__global__ void k_scatter(const int* __restrict__ src,
                          const int* __restrict__ dst, int E, int n) {
    int e = blockIdx.x * blockDim.x + threadIdx.x;
    if (e >= E) return;
    int s = src[e];
    int d = dst[e];
    if ((unsigned)s >= (unsigned)n || (unsigned)d >= (unsigned)n) return;
    int pos = atomicAdd(&g_cursor[d], 1);
    g_edge[pos] = make_int2(s, __float_as_int(g_dis[s] * g_dis[d]));
}

// ---------------- HMMA GEMM: C[M,N] = A[M,128] @ Wt[N,128]^T, bf16 split ----------------
template <int N>
__global__ void __launch_bounds__(256) k_gemm_tc(const float* __restrict__ A,
                                                 const __nv_bfloat16* __restrict__ Bh,
                                                 const __nv_bfloat16* __restrict__ Bl,
                                                 float* __restrict__ C, int M) {
    constexpr int NT = N / 8;
    constexpr int A_ELE = 128 * LDA;
    constexpr int B_ELE = N * LDA;
    extern __shared__ __nv_bfloat16 sm[];
    __nv_bfloat16* sAh = sm;
    __nv_bfloat16* sAl = sm + A_ELE;
    __nv_bfloat16* sBh = sm + 2 * A_ELE;
    __nv_bfloat16* sBl = sm + 2 * A_ELE + B_ELE;

    int tid = threadIdx.x, wid = tid >> 5, lane = tid & 31;
    int row0 = blockIdx.x * 128;

    {
        const uint4* bh = (const uint4*)Bh;
        const uint4* bl = (const uint4*)Bl;
        for (int i = tid; i < N * 16; i += 256) {
            int r = i >> 4, c = i & 15;
            int d = r * LDA + c * 8;
            *(uint4*)(sBh + d) = bh[i];
            *(uint4*)(sBl + d) = bl[i];
        }
    }
    {
        for (int i = tid; i < 128 * 32; i += 256) {
            int r = i >> 5, c = i & 31;
            int grow = row0 + r;
            float4 f = (grow < M) ? ((const float4*)A)[(size_t)grow * 32 + c]
                                  : make_float4(0.f, 0.f, 0.f, 0.f);
            __nv_bfloat16 hx = __float2bfloat16(f.x), hy = __float2bfloat16(f.y);
            __nv_bfloat16 hz = __float2bfloat16(f.z), hw = __float2bfloat16(f.w);
            uint32_t h01 = pack_bf16x2(hx, hy), h23 = pack_bf16x2(hz, hw);
            uint32_t l01 = pack_bf16x2(__float2bfloat16(f.x - __bfloat162float(hx)),
                                       __float2bfloat16(f.y - __bfloat162float(hy)));
            uint32_t l23 = pack_bf16x2(__float2bfloat16(f.z - __bfloat162float(hz)),
                                       __float2bfloat16(f.w - __bfloat162float(hw)));
            int d = r * LDA + c * 4;
            *(uint32_t*)(sAh + d) = h01; *(uint32_t*)(sAh + d + 2) = h23;
            *(uint32_t*)(sAl + d) = l01; *(uint32_t*)(sAl + d + 2) = l23;
        }
    }
    __syncthreads();

    uint32_t aOff = (uint32_t)(wid * 16 + (lane & 15)) * (LDA * 2) + (uint32_t)(lane >> 4) * 16;
    uint32_t ah_base = smem_u32(sAh) + aOff;
    uint32_t al_base = smem_u32(sAl) + aOff;
    uint32_t bOff = (uint32_t)(lane & 7) * (LDA * 2) + (uint32_t)((lane >> 3) & 1) * 16;
    uint32_t bh_base = smem_u32(sBh) + bOff;
    uint32_t bl_base = smem_u32(sBl) + bOff;

    float acc[NT][4];
    #pragma unroll
    for (int t = 0; t < NT; t++) { acc[t][0] = acc[t][1] = acc[t][2] = acc[t][3] = 0.f; }

    #pragma unroll
    for (int kk = 0; kk < 8; kk++) {
        uint32_t ah[4], al[4];
        ldmatrix_x4(ah[0], ah[1], ah[2], ah[3], ah_base + kk * 32);
        ldmatrix_x4(al[0], al[1], al[2], al[3], al_base + kk * 32);
        #pragma unroll
        for (int t = 0; t < NT; t++) {
            uint32_t b0, b1, c0, c1;
            uint32_t boff = (uint32_t)t * 8 * (LDA * 2) + kk * 32;
            ldmatrix_x2(b0, b1, bh_base + boff);
            ldmatrix_x2(c0, c1, bl_base + boff);
            mma_bf16(acc[t], ah, b0, b1);
            mma_bf16(acc[t], ah, c0, c1);
            mma_bf16(acc[t], al, b0, b1);
        }
    }

    int g = lane >> 2, tig = lane & 3;
    int r0 = row0 + wid * 16 + g;
    int r1 = r0 + 8;
    #pragma unroll
    for (int t = 0; t < NT; t++) {
        int col = t * 8 + tig * 2;
        if (r0 < M) *(float2*)(C + (size_t)r0 * N + col) = make_float2(acc[t][0], acc[t][1]);
        if (r1 < M) *(float2*)(C + (size_t)r1 * N + col) = make_float2(acc[t][2], acc[t][3]);
    }
}

// ---------------- aggregation: warp/node, 128 features ----------------
template <bool RELU>
__global__ void k_agg128(const float* __restrict__ h,
                         const float* __restrict__ bias,
                         float* __restrict__ out, int n) {
    int gwarp = (blockIdx.x * blockDim.x + threadIdx.x) >> 5;
    if (gwarp >= n) return;
    int lane = threadIdx.x & 31;
    const float4* hv = (const float4*)h;
    float d = g_dis[gwarp];
    float4 v = hv[gwarp * 32 + lane];
    float sn = d * d;
    float4 acc = make_float4(sn * v.x, sn * v.y, sn * v.z, sn * v.w);
    int e = g_rowptr[gwarp], e1 = g_rowptr[gwarp + 1];
    for (; e + 4 <= e1; e += 4) {
        int2 q0 = g_edge[e + 0], q1 = g_edge[e + 1], q2 = g_edge[e + 2], q3 = g_edge[e + 3];
        float n0 = __int_as_float(q0.y), n1 = __int_as_float(q1.y);
        float n2 = __int_as_float(q2.y), n3 = __int_as_float(q3.y);
        float4 v0 = hv[q0.x * 32 + lane];
        float4 v1 = hv[q1.x * 32 + lane];
        float4 v2 = hv[q2.x * 32 + lane];
        float4 v3 = hv[q3.x * 32 + lane];
        acc.x += n0 * v0.x + n1 * v1.x + n2 * v2.x + n3 * v3.x;
        acc.y += n0 * v0.y + n1 * v1.y + n2 * v2.y + n3 * v3.y;
        acc.z += n0 * v0.z + n1 * v1.z + n2 * v2.z + n3 * v3.z;
        acc.w += n0 * v0.w + n1 * v1.w + n2 * v2.w + n3 * v3.w;
    }
    for (; e < e1; e++) {
        int2 q = g_edge[e];
        float nm = __int_as_float(q.y);
        float4 vv = hv[q.x * 32 + lane];
        acc.x += nm * vv.x; acc.y += nm * vv.y;
        acc.z += nm * vv.z; acc.w += nm * vv.w;
    }
    float4 b = ((const float4*)bias)[lane];
    acc.x += b.x; acc.y += b.y; acc.z += b.z; acc.w += b.w;
    if (RELU) {
        acc.x = fmaxf(acc.x, 0.f); acc.y = fmaxf(acc.y, 0.f);
        acc.z = fmaxf(acc.z, 0.f); acc.w = fmaxf(acc.w, 0.f);
    }
    ((float4*)out)[gwarp * 32 + lane] = acc;
}

// ---------------- aggregation: warp/node, 64 features ----------------
template <bool RELU>
__global__ void k_agg64(const float* __restrict__ h,
                        const float* __restrict__ bias,
                        float* __restrict__ out, int n) {
    int gwarp = (blockIdx.x * blockDim.x + threadIdx.x) >> 5;
    if (gwarp >= n) return;
    int lane = threadIdx.x & 31;
    const float2* hv = (const float2*)h;
    float d = g_dis[gwarp];
    float2 v = hv[gwarp * 32 + lane];
    float sn = d * d;
    float2 acc = make_float2(sn * v.x, sn * v.y);
    int e = g_rowptr[gwarp], e1 = g_rowptr[gwarp + 1];
    for (; e + 4 <= e1; e += 4) {
        int2 q0 = g_edge[e + 0], q1 = g_edge[e + 1], q2 = g_edge[e + 2], q3 = g_edge[e + 3];
        float n0 = __int_as_float(q0.y), n1 = __int_as_float(q1.y);
        float n2 = __int_as_float(q2.y), n3 = __int_as_float(q3.y);
        float2 v0 = hv[q0.x * 32 + lane];
        float2 v1 = hv[q1.x * 32 + lane];
        float2 v2 = hv[q2.x * 32 + lane];
        float2 v3 = hv[q3.x * 32 + lane];
        acc.x += n0 * v0.x + n1 * v1.x + n2 * v2.x + n3 * v3.x;
        acc.y += n0 * v0.y + n1 * v1.y + n2 * v2.y + n3 * v3.y;
    }
    for (; e < e1; e++) {
        int2 q = g_edge[e];
        float nm = __int_as_float(q.y);
        float2 vv = hv[q.x * 32 + lane];
        acc.x += nm * vv.x; acc.y += nm * vv.y;
    }
    float2 b = ((const float2*)bias)[lane];
    acc.x += b.x; acc.y += b.y;
    if (RELU) { acc.x = fmaxf(acc.x, 0.f); acc.y = fmaxf(acc.y, 0.f); }
    ((float2*)out)[gwarp * 32 + lane] = acc;
}

// ---------------- launch ----------------
extern "C" void kernel_launch(void* const* d_in, const int* in_sizes, int n_in,
                              void* d_out, int out_size) {
    const float* x    = (const float*)d_in[0];
    const int*   eidx = (const int*)d_in[1];
    const float* W1   = (const float*)d_in[2];
    const float* b1   = (const float*)d_in[3];
    const float* W2   = (const float*)d_in[4];
    const float* b2   = (const float*)d_in[5];
    float*       out  = (float*)d_out;

    int n = in_sizes[0] / F_IN;
    int E = in_sizes[1] / 2;
    const int* src = eidx;
    const int* dst = eidx + E;
    int nb = (n + SCAN_CHUNK - 1) / SCAN_CHUNK;

    const int SMEM1 = (2 * 128 * LDA + 2 * 128 * LDA) * 2;   // 139264 B
    const int SMEM2 = (2 * 128 * LDA + 2 * 64 * LDA) * 2;    // 104448 B
    cudaFuncSetAttribute(k_gemm_tc<128>, cudaFuncAttributeMaxDynamicSharedMemorySize, SMEM1);
    cudaFuncSetAttribute(k_gemm_tc<64>,  cudaFuncAttributeMaxDynamicSharedMemorySize, SMEM2);

    float* h1;  cudaGetSymbolAddress((void**)&h1, g_h1);
    float* a1;  cudaGetSymbolAddress((void**)&a1, g_a1);
    float* h2;  cudaGetSymbolAddress((void**)&h2, g_h2);
    int* degp;  cudaGetSymbolAddress((void**)&degp, g_deg);
    __nv_bfloat16 *w1h, *w1l, *w2h, *w2l;
    cudaGetSymbolAddress((void**)&w1h, g_w1h);
    cudaGetSymbolAddress((void**)&w1l, g_w1l);
    cudaGetSymbolAddress((void**)&w2h, g_w2h);
    cudaGetSymbolAddress((void**)&w2l, g_w2l);

    // graph structure build (3 kernels + 1 memset)
    cudaMemsetAsync(degp, 0, (size_t)n * sizeof(int), 0);
    k_prep<<<(W_ELEMS + E + 255) / 256, 256>>>(W1, W2, dst, E, n);
    k_scan<<<nb, 1024>>>(n, nb);
    k_scatter<<<(E + 255) / 256, 256>>>(src, dst, E, n);

    int aggBlocks = (n + 7) / 8;
    int gemmBlocks = (n + 127) / 128;

    // layer 1
    k_gemm_tc<128><<<gemmBlocks, 256, SMEM1>>>(x, w1h, w1l, h1, n);
    k_agg128<true><<<aggBlocks, 256>>>(h1, b1, a1, n);
    // layer 2
    k_gemm_tc<64><<<gemmBlocks, 256, SMEM2>>>(a1, w2h, w2l, h2, n);
    k_agg64<false><<<aggBlocks, 256>>>(h2, b2, out, n);
}

// round 13
// speedup vs baseline: 1.4931x; 1.2207x over previous
#include <cuda_runtime.h>
#include <cuda_bf16.h>
#include <cstdint>
#include <math.h>

// ---------------- problem constants ----------------
#define F_IN  128
#define D1    128
#define N_CLS 64
#define MAXN  50000
#define MAXE  800000
#define SCAN_CHUNK 4096
#define MAXB ((MAXN + SCAN_CHUNK - 1) / SCAN_CHUNK)
#define LDA 136   // padded smem row pitch in bf16 (272 B)
#define W_ELEMS (128 * 128 + 64 * 128)   // 24576

// ---------------- device scratch ----------------
__device__ float g_h1[MAXN * D1];
__device__ float g_a1[MAXN * D1];
__device__ float g_h2[MAXN * N_CLS];
__device__ int   g_deg[MAXN];
__device__ float g_dis[MAXN];
__device__ int   g_rowptr[MAXN + 1];
__device__ int   g_cursor[MAXN];
__device__ int2  g_edge[MAXE];                 // (src, norm-bits)
__device__ unsigned long long g_state[MAXB];   // lookback: flag<<32 | value
// bf16-split transposed weights, plain [N][128] row-major
__device__ __nv_bfloat16 g_w1h[128 * 128];
__device__ __nv_bfloat16 g_w1l[128 * 128];
__device__ __nv_bfloat16 g_w2h[64 * 128];
__device__ __nv_bfloat16 g_w2l[64 * 128];

// ---------------- helpers ----------------
__device__ __forceinline__ uint32_t smem_u32(const void* p) {
    uint32_t a;
    asm("{ .reg .u64 t; cvta.to.shared.u64 t, %1; cvt.u32.u64 %0, t; }" : "=r"(a) : "l"(p));
    return a;
}
__device__ __forceinline__ void ldmatrix_x2(uint32_t& r0, uint32_t& r1, uint32_t addr) {
    asm volatile("ldmatrix.sync.aligned.m8n8.x2.shared.b16 {%0,%1}, [%2];"
                 : "=r"(r0), "=r"(r1) : "r"(addr));
}
__device__ __forceinline__ void mma_bf16(float* c, const uint32_t* a, uint32_t b0, uint32_t b1) {
    asm volatile("mma.sync.aligned.m16n8k16.row.col.f32.bf16.bf16.f32 "
                 "{%0,%1,%2,%3}, {%4,%5,%6,%7}, {%8,%9}, {%0,%1,%2,%3};"
                 : "+f"(c[0]), "+f"(c[1]), "+f"(c[2]), "+f"(c[3])
                 : "r"(a[0]), "r"(a[1]), "r"(a[2]), "r"(a[3]), "r"(b0), "r"(b1));
}
__device__ __forceinline__ uint32_t pack_bf16x2(__nv_bfloat16 lo, __nv_bfloat16 hi) {
    return ((uint32_t)__bfloat16_as_ushort(hi) << 16) | (uint32_t)__bfloat16_as_ushort(lo);
}
// split a float2 into hi-bf16x2 and lo-bf16x2 (residual)
__device__ __forceinline__ void split2(float2 f, uint32_t& h, uint32_t& l) {
    __nv_bfloat16 hx = __float2bfloat16(f.x), hy = __float2bfloat16(f.y);
    h = pack_bf16x2(hx, hy);
    l = pack_bf16x2(__float2bfloat16(f.x - __bfloat162float(hx)),
                    __float2bfloat16(f.y - __bfloat162float(hy)));
}

// ---------------- fused prep: weight split/transpose + degree count + state zero ----------------
__global__ void k_prep(const float* __restrict__ W1, const float* __restrict__ W2,
                       const int* __restrict__ dst, int E, int n) {
    int idx = blockIdx.x * blockDim.x + threadIdx.x;
    if (idx < MAXB) g_state[idx] = 0ull;
    if (idx < 128 * 128) {
        int nn = idx >> 7, k = idx & 127;
        float w = W1[k * 128 + nn];
        __nv_bfloat16 h = __float2bfloat16(w);
        g_w1h[idx] = h;
        g_w1l[idx] = __float2bfloat16(w - __bfloat162float(h));
    } else if (idx < W_ELEMS) {
        int j = idx - 16384;
        int nn = j >> 7, k = j & 127;
        float w = W2[k * 64 + nn];
        __nv_bfloat16 h = __float2bfloat16(w);
        g_w2h[j] = h;
        g_w2l[j] = __float2bfloat16(w - __bfloat162float(h));
    } else {
        int e = idx - W_ELEMS;
        if (e < E) {
            int d = dst[e];
            if ((unsigned)d < (unsigned)n) atomicAdd(&g_deg[d], 1);
        }
    }
}

// ---------------- single-pass decoupled-lookback scan ----------------
__global__ void __launch_bounds__(1024) k_scan(int n, int nb) {
    __shared__ int wsum[32];
    __shared__ int carry_s;
    int tid = threadIdx.x, lane = tid & 31, wid = tid >> 5;
    int bid = blockIdx.x;
    int base = bid * SCAN_CHUNK + tid * 4;

    int v[4];
    #pragma unroll
    for (int j = 0; j < 4; j++) {
        int i = base + j;
        int raw = (i < n) ? g_deg[i] : 0;
        v[j] = raw;
        if (i < n) g_dis[i] = rsqrtf((float)(raw + 1));
    }
    int tsum = v[0] + v[1] + v[2] + v[3];
    int x = tsum;
    #pragma unroll
    for (int off = 1; off < 32; off <<= 1) {
        int y = __shfl_up_sync(0xffffffffu, x, off);
        if (lane >= off) x += y;
    }
    if (lane == 31) wsum[wid] = x;
    __syncthreads();
    if (wid == 0) {
        int w = wsum[lane];
        #pragma unroll
        for (int off = 1; off < 32; off <<= 1) {
            int y = __shfl_up_sync(0xffffffffu, w, off);
            if (lane >= off) w += y;
        }
        wsum[lane] = w;
    }
    __syncthreads();
    int total = wsum[31];
    int excl = (wid ? wsum[wid - 1] : 0) + (x - tsum);

    if (tid == 0) {
        if (bid == 0) {
            atomicExch(&g_state[0], (2ull << 32) | (unsigned long long)(unsigned)total);
            carry_s = 0;
        } else {
            atomicExch(&g_state[bid], (1ull << 32) | (unsigned long long)(unsigned)total);
            int carry = 0;
            for (int j = bid - 1; j >= 0; j--) {
                unsigned long long s;
                do { s = atomicAdd(&g_state[j], 0ull); } while ((s >> 32) == 0ull);
                carry += (int)(unsigned)s;
                if ((s >> 32) == 2ull) break;
            }
            atomicExch(&g_state[bid], (2ull << 32) | (unsigned long long)(unsigned)(total + carry));
            carry_s = carry;
        }
    }
    __syncthreads();

    int e = excl + carry_s;
    #pragma unroll
    for (int j = 0; j < 4; j++) {
        int i = base + j;
        if (i < n) { g_rowptr[i] = e; g_cursor[i] = e; }
        e += v[j];
    }
    if (bid == nb - 1 && tid == 1023) g_rowptr[n] = carry_s + total;
}

// ---------------- scatter (packed src+norm) ----------------
__global__ void k_scatter(const int* __restrict__ src,
                          const int* __restrict__ dst, int E, int n) {
    int e = blockIdx.x * blockDim.x + threadIdx.x;
    if (e >= E) return;
    int s = src[e];
    int d = dst[e];
    if ((unsigned)s >= (unsigned)n || (unsigned)d >= (unsigned)n) return;
    int pos = atomicAdd(&g_cursor[d], 1);
    g_edge[pos] = make_int2(s, __float_as_int(g_dis[s] * g_dis[d]));
}

// ---------------- HMMA GEMM: C[M,N] = A[M,128] @ Wt[N,128]^T, bf16 split ----------------
// block = 256 threads (8 warps), M-tile 128; A fragments loaded DIRECTLY from
// gmem per the documented m16n8k16 lane layout (no A smem staging).
// smem holds only B (hi+lo) -> 2 CTAs/SM.
template <int N>
__global__ void __launch_bounds__(256, 2) k_gemm_tc(const float* __restrict__ A,
                                                    const __nv_bfloat16* __restrict__ Bh,
                                                    const __nv_bfloat16* __restrict__ Bl,
                                                    float* __restrict__ C, int M) {
    constexpr int NT = N / 8;
    constexpr int B_ELE = N * LDA;
    extern __shared__ __nv_bfloat16 sm[];
    __nv_bfloat16* sBh = sm;
    __nv_bfloat16* sBl = sm + B_ELE;

    int tid = threadIdx.x, wid = tid >> 5, lane = tid & 31;
    int row0 = blockIdx.x * 128;

    // stage B (16 uint4 = 128 bf16 per row)
    {
        const uint4* bh = (const uint4*)Bh;
        const uint4* bl = (const uint4*)Bl;
        for (int i = tid; i < N * 16; i += 256) {
            int r = i >> 4, c = i & 15;
            int d = r * LDA + c * 8;
            *(uint4*)(sBh + d) = bh[i];
            *(uint4*)(sBl + d) = bl[i];
        }
    }
    __syncthreads();

    // A direct-load lane mapping (m16n8k16 row-major A fragment)
    int g = lane >> 2;            // 0..7
    int c0 = (lane & 3) * 2;      // 0,2,4,6
    int r0 = row0 + wid * 16 + g;
    int r1 = r0 + 8;
    bool v0 = r0 < M, v1 = r1 < M;
    const float* a0p = A + (size_t)(v0 ? r0 : 0) * 128;
    const float* a1p = A + (size_t)(v1 ? r1 : 0) * 128;

    uint32_t bOff = (uint32_t)(lane & 7) * (LDA * 2) + (uint32_t)((lane >> 3) & 1) * 16;
    uint32_t bh_base = smem_u32(sBh) + bOff;
    uint32_t bl_base = smem_u32(sBl) + bOff;

    float acc[NT][4];
    #pragma unroll
    for (int t = 0; t < NT; t++) { acc[t][0] = acc[t][1] = acc[t][2] = acc[t][3] = 0.f; }

    const float2 f2z = make_float2(0.f, 0.f);
    #pragma unroll
    for (int kk = 0; kk < 8; kk++) {
        int k0 = kk * 16 + c0;
        float2 f00 = v0 ? *(const float2*)(a0p + k0)     : f2z;   // a0: row g,   k 0..7
        float2 f10 = v1 ? *(const float2*)(a1p + k0)     : f2z;   // a1: row g+8, k 0..7
        float2 f01 = v0 ? *(const float2*)(a0p + k0 + 8) : f2z;   // a2: row g,   k 8..15
        float2 f11 = v1 ? *(const float2*)(a1p + k0 + 8) : f2z;   // a3: row g+8, k 8..15
        uint32_t ah[4], al[4];
        split2(f00, ah[0], al[0]);
        split2(f10, ah[1], al[1]);
        split2(f01, ah[2], al[2]);
        split2(f11, ah[3], al[3]);
        #pragma unroll
        for (int t = 0; t < NT; t++) {
            uint32_t b0, b1, d0, d1;
            uint32_t boff = (uint32_t)t * 8 * (LDA * 2) + kk * 32;
            ldmatrix_x2(b0, b1, bh_base + boff);
            ldmatrix_x2(d0, d1, bl_base + boff);
            mma_bf16(acc[t], ah, b0, b1);   // Ah*Bh
            mma_bf16(acc[t], ah, d0, d1);   // Ah*Bl
            mma_bf16(acc[t], al, b0, b1);   // Al*Bh
        }
    }

    int tig = lane & 3;
    #pragma unroll
    for (int t = 0; t < NT; t++) {
        int col = t * 8 + tig * 2;
        if (v0) *(float2*)(C + (size_t)r0 * N + col) = make_float2(acc[t][0], acc[t][1]);
        if (v1) *(float2*)(C + (size_t)r1 * N + col) = make_float2(acc[t][2], acc[t][3]);
    }
}

// ---------------- aggregation: warp/node, 128 features ----------------
template <bool RELU>
__global__ void k_agg128(const float* __restrict__ h,
                         const float* __restrict__ bias,
                         float* __restrict__ out, int n) {
    int gwarp = (blockIdx.x * blockDim.x + threadIdx.x) >> 5;
    if (gwarp >= n) return;
    int lane = threadIdx.x & 31;
    const float4* hv = (const float4*)h;
    float d = g_dis[gwarp];
    float4 v = hv[gwarp * 32 + lane];
    float sn = d * d;
    float4 acc = make_float4(sn * v.x, sn * v.y, sn * v.z, sn * v.w);
    int e = g_rowptr[gwarp], e1 = g_rowptr[gwarp + 1];
    for (; e + 4 <= e1; e += 4) {
        int2 q0 = g_edge[e + 0], q1 = g_edge[e + 1], q2 = g_edge[e + 2], q3 = g_edge[e + 3];
        float n0 = __int_as_float(q0.y), n1 = __int_as_float(q1.y);
        float n2 = __int_as_float(q2.y), n3 = __int_as_float(q3.y);
        float4 v0 = hv[q0.x * 32 + lane];
        float4 v1 = hv[q1.x * 32 + lane];
        float4 v2 = hv[q2.x * 32 + lane];
        float4 v3 = hv[q3.x * 32 + lane];
        acc.x += n0 * v0.x + n1 * v1.x + n2 * v2.x + n3 * v3.x;
        acc.y += n0 * v0.y + n1 * v1.y + n2 * v2.y + n3 * v3.y;
        acc.z += n0 * v0.z + n1 * v1.z + n2 * v2.z + n3 * v3.z;
        acc.w += n0 * v0.w + n1 * v1.w + n2 * v2.w + n3 * v3.w;
    }
    for (; e < e1; e++) {
        int2 q = g_edge[e];
        float nm = __int_as_float(q.y);
        float4 vv = hv[q.x * 32 + lane];
        acc.x += nm * vv.x; acc.y += nm * vv.y;
        acc.z += nm * vv.z; acc.w += nm * vv.w;
    }
    float4 b = ((const float4*)bias)[lane];
    acc.x += b.x; acc.y += b.y; acc.z += b.z; acc.w += b.w;
    if (RELU) {
        acc.x = fmaxf(acc.x, 0.f); acc.y = fmaxf(acc.y, 0.f);
        acc.z = fmaxf(acc.z, 0.f); acc.w = fmaxf(acc.w, 0.f);
    }
    ((float4*)out)[gwarp * 32 + lane] = acc;
}

// ---------------- aggregation: warp/node, 64 features ----------------
template <bool RELU>
__global__ void k_agg64(const float* __restrict__ h,
                        const float* __restrict__ bias,
                        float* __restrict__ out, int n) {
    int gwarp = (blockIdx.x * blockDim.x + threadIdx.x) >> 5;
    if (gwarp >= n) return;
    int lane = threadIdx.x & 31;
    const float2* hv = (const float2*)h;
    float d = g_dis[gwarp];
    float2 v = hv[gwarp * 32 + lane];
    float sn = d * d;
    float2 acc = make_float2(sn * v.x, sn * v.y);
    int e = g_rowptr[gwarp], e1 = g_rowptr[gwarp + 1];
    for (; e + 4 <= e1; e += 4) {
        int2 q0 = g_edge[e + 0], q1 = g_edge[e + 1], q2 = g_edge[e + 2], q3 = g_edge[e + 3];
        float n0 = __int_as_float(q0.y), n1 = __int_as_float(q1.y);
        float n2 = __int_as_float(q2.y), n3 = __int_as_float(q3.y);
        float2 v0 = hv[q0.x * 32 + lane];
        float2 v1 = hv[q1.x * 32 + lane];
        float2 v2 = hv[q2.x * 32 + lane];
        float2 v3 = hv[q3.x * 32 + lane];
        acc.x += n0 * v0.x + n1 * v1.x + n2 * v2.x + n3 * v3.x;
        acc.y += n0 * v0.y + n1 * v1.y + n2 * v2.y + n3 * v3.y;
    }
    for (; e < e1; e++) {
        int2 q = g_edge[e];
        float nm = __int_as_float(q.y);
        float2 vv = hv[q.x * 32 + lane];
        acc.x += nm * vv.x; acc.y += nm * vv.y;
    }
    float2 b = ((const float2*)bias)[lane];
    acc.x += b.x; acc.y += b.y;
    if (RELU) { acc.x = fmaxf(acc.x, 0.f); acc.y = fmaxf(acc.y, 0.f); }
    ((float2*)out)[gwarp * 32 + lane] = acc;
}

// ---------------- launch ----------------
extern "C" void kernel_launch(void* const* d_in, const int* in_sizes, int n_in,
                              void* d_out, int out_size) {
    const float* x    = (const float*)d_in[0];
    const int*   eidx = (const int*)d_in[1];
    const float* W1   = (const float*)d_in[2];
    const float* b1   = (const float*)d_in[3];
    const float* W2   = (const float*)d_in[4];
    const float* b2   = (const float*)d_in[5];
    float*       out  = (float*)d_out;

    int n = in_sizes[0] / F_IN;
    int E = in_sizes[1] / 2;
    const int* src = eidx;
    const int* dst = eidx + E;
    int nb = (n + SCAN_CHUNK - 1) / SCAN_CHUNK;

    const int SMEM1 = 2 * 128 * LDA * 2;   // 69632 B (B hi+lo only)
    const int SMEM2 = 2 * 64 * LDA * 2;    // 34816 B
    cudaFuncSetAttribute(k_gemm_tc<128>, cudaFuncAttributeMaxDynamicSharedMemorySize, SMEM1);
    cudaFuncSetAttribute(k_gemm_tc<64>,  cudaFuncAttributeMaxDynamicSharedMemorySize, SMEM2);

    float* h1;  cudaGetSymbolAddress((void**)&h1, g_h1);
    float* a1;  cudaGetSymbolAddress((void**)&a1, g_a1);
    float* h2;  cudaGetSymbolAddress((void**)&h2, g_h2);
    int* degp;  cudaGetSymbolAddress((void**)&degp, g_deg);
    __nv_bfloat16 *w1h, *w1l, *w2h, *w2l;
    cudaGetSymbolAddress((void**)&w1h, g_w1h);
    cudaGetSymbolAddress((void**)&w1l, g_w1l);
    cudaGetSymbolAddress((void**)&w2h, g_w2h);
    cudaGetSymbolAddress((void**)&w2l, g_w2l);

    // graph structure build (3 kernels + 1 memset)
    cudaMemsetAsync(degp, 0, (size_t)n * sizeof(int), 0);
    k_prep<<<(W_ELEMS + E + 255) / 256, 256>>>(W1, W2, dst, E, n);
    k_scan<<<nb, 1024>>>(n, nb);
    k_scatter<<<(E + 255) / 256, 256>>>(src, dst, E, n);

    int aggBlocks = (n + 7) / 8;
    int gemmBlocks = (n + 127) / 128;

    // layer 1
    k_gemm_tc<128><<<gemmBlocks, 256, SMEM1>>>(x, w1h, w1l, h1, n);
    k_agg128<true><<<aggBlocks, 256>>>(h1, b1, a1, n);
    // layer 2
    k_gemm_tc<64><<<gemmBlocks, 256, SMEM2>>>(a1, w2h, w2l, h2, n);
    k_agg64<false><<<aggBlocks, 256>>>(h2, b2, out, n);
}